// round 1
// baseline (speedup 1.0000x reference)
#include <cuda_runtime.h>
#include <math.h>

// Problem constants
#define BB 2
#define LL 1024
#define DIN 512
#define DM 1024
#define DS 16
#define DD 64
#define KERW 4
#define TOK (BB * LL)   // 2048 tokens
#define CHUNK 64
#define NCH (LL / CHUNK) // 16

// ---------------- scratch (static device globals; no allocation) -------------
__device__ __align__(16) float g_ab[TOK * 2 * DM];       // 16 MB  (a_lin | bgate)
__device__ __align__(16) float g_x[TOK * DM];            // 8 MB   conv+silu output
__device__ __align__(16) float g_bcd[TOK * 96];          //        [Bm|Cm|xd1]
__device__ __align__(16) float g_delta[TOK * DM];        // 8 MB
__device__ __align__(16) float g_wbcd[96 * DM];          //        packed [W_B;W_C;W_D1]
__device__ __align__(16) float g_hend[BB * NCH * DS * DM];
__device__ __align__(16) float g_pd[BB * NCH * DM];
__device__ __align__(16) float g_hinit[BB * NCH * DS * DM];
__device__ __align__(16) float g_obuf[TOK * DM];         // 8 MB   ssm_out * silu(b)

// ---------------- generic fp32 GEMM:  C[M,N] = A[M,K] * W[N,K]^T -------------
#define BM 128
#define BN 64
#define BK 16

__global__ __launch_bounds__(256) void sgemm_nt(
    const float* __restrict__ A, int lda,
    const float* __restrict__ W,
    float* __restrict__ C,
    int M, int N, int K)
{
    __shared__ float As[BK][BM];
    __shared__ float Bs[BK][BN];

    const int bm = blockIdx.y * BM;
    const int bn = blockIdx.x * BN;
    const int tid = threadIdx.x;
    const int tx = tid & 15;        // 16 threads * 4 cols = 64 (N)
    const int ty = tid >> 4;        // 16 threads * 8 rows = 128 (M)
    const int lrow = tid >> 2;      // 0..63
    const int lcol = (tid & 3) << 2;// 0,4,8,12

    float acc[8][4];
#pragma unroll
    for (int i = 0; i < 8; i++)
#pragma unroll
        for (int j = 0; j < 4; j++) acc[i][j] = 0.f;

    for (int k0 = 0; k0 < K; k0 += BK) {
        float4 a0 = *(const float4*)(A + (size_t)(bm + lrow) * lda + k0 + lcol);
        float4 a1 = *(const float4*)(A + (size_t)(bm + lrow + 64) * lda + k0 + lcol);
        float4 b0;
        if (bn + lrow < N)
            b0 = *(const float4*)(W + (size_t)(bn + lrow) * K + k0 + lcol);
        else
            b0 = make_float4(0.f, 0.f, 0.f, 0.f);

        __syncthreads();  // previous tile's compute finished before overwrite

        As[lcol + 0][lrow] = a0.x;  As[lcol + 1][lrow] = a0.y;
        As[lcol + 2][lrow] = a0.z;  As[lcol + 3][lrow] = a0.w;
        As[lcol + 0][lrow + 64] = a1.x;  As[lcol + 1][lrow + 64] = a1.y;
        As[lcol + 2][lrow + 64] = a1.z;  As[lcol + 3][lrow + 64] = a1.w;
        Bs[lcol + 0][lrow] = b0.x;  Bs[lcol + 1][lrow] = b0.y;
        Bs[lcol + 2][lrow] = b0.z;  Bs[lcol + 3][lrow] = b0.w;

        __syncthreads();

#pragma unroll
        for (int kk = 0; kk < BK; kk++) {
            float a[8], bv[4];
            *(float4*)(a + 0) = *(const float4*)&As[kk][ty * 8];
            *(float4*)(a + 4) = *(const float4*)&As[kk][ty * 8 + 4];
            *(float4*)(bv)    = *(const float4*)&Bs[kk][tx * 4];
#pragma unroll
            for (int i = 0; i < 8; i++)
#pragma unroll
                for (int j = 0; j < 4; j++)
                    acc[i][j] += a[i] * bv[j];
        }
    }

#pragma unroll
    for (int i = 0; i < 8; i++) {
        int row = bm + ty * 8 + i;
#pragma unroll
        for (int j = 0; j < 4; j++) {
            int col = bn + tx * 4 + j;
            if (col < N) C[(size_t)row * N + col] = acc[i][j];
        }
    }
}

// ---------------- pack W_B, W_C, W_D1 into one [96,1024] matrix --------------
__global__ void pack_w(const float* __restrict__ WB, const float* __restrict__ WC,
                       const float* __restrict__ WD1)
{
    int i = blockIdx.x * 256 + threadIdx.x;
    if (i < 16 * DM)       g_wbcd[i] = WB[i];
    else if (i < 32 * DM)  g_wbcd[i] = WC[i - 16 * DM];
    else if (i < 96 * DM)  g_wbcd[i] = WD1[i - 32 * DM];
}

// ---------------- causal depthwise conv (K=4) + SiLU -------------------------
__global__ void conv_silu(const float* __restrict__ cw, const float* __restrict__ cb)
{
    int idx = blockIdx.x * 256 + threadIdx.x;
    if (idx >= TOK * DM) return;
    int d = idx & (DM - 1);
    int t = idx >> 10;          // token index b*L + l
    int l = t & (LL - 1);
    float acc = cb[d];
#pragma unroll
    for (int k = 0; k < KERW; k++) {
        int ll = l - (KERW - 1) + k;
        if (ll >= 0)
            acc += g_ab[(size_t)(t - l + ll) * (2 * DM) + d] * cw[d * KERW + k];
    }
    float s = acc / (1.f + expf(-acc));
    g_x[idx] = s;
}

// ---------------- delta = softplus(D + delta_lin) (in place on g_delta) ------
__global__ void softplus_delta(const float* __restrict__ Dvec)
{
    int idx = blockIdx.x * 256 + threadIdx.x;
    if (idx >= TOK * DM) return;
    int d = idx & (DM - 1);
    float z = Dvec[d] + g_delta[idx];
    // stable softplus: max(z,0) + log1p(exp(-|z|))
    g_delta[idx] = fmaxf(z, 0.f) + log1pf(expf(-fabsf(z)));
}

// ---------------- SSM scan, phase 1: per-chunk local scan --------------------
__global__ __launch_bounds__(128) void scan_phase1(const float* __restrict__ Avec)
{
    __shared__ float Bsm[CHUNK * 16];
    int d = blockIdx.x * 128 + threadIdx.x;
    int c = blockIdx.y;
    int b = blockIdx.z;
    int base_tok = b * LL + c * CHUNK;

    for (int i = threadIdx.x; i < CHUNK * 16; i += 128) {
        int l = i >> 4, s = i & 15;
        Bsm[i] = g_bcd[(size_t)(base_tok + l) * 96 + s];
    }
    __syncthreads();

    float E[16];
#pragma unroll
    for (int s = 0; s < 16; s++) E[s] = expf(-Avec[d * 16 + s]);

    float h[16];
#pragma unroll
    for (int s = 0; s < 16; s++) h[s] = 0.f;
    float pd = 1.f;

    for (int l = 0; l < CHUNK; l++) {
        int tok = base_tok + l;
        float dl = g_delta[(size_t)tok * DM + d];
        float xv = g_x[(size_t)tok * DM + d];
        float dx = dl * xv;
        pd *= dl;
#pragma unroll
        for (int s = 0; s < 16; s++)
            h[s] = E[s] * dl * h[s] + Bsm[l * 16 + s] * dx;
    }

    int cb = b * NCH + c;
    g_pd[(size_t)cb * DM + d] = pd;
#pragma unroll
    for (int s = 0; s < 16; s++)
        g_hend[((size_t)cb * 16 + s) * DM + d] = h[s];
}

// ---------------- SSM scan, phase 2: sequential chunk combine ---------------
__global__ __launch_bounds__(256) void scan_phase2(const float* __restrict__ Avec)
{
    int gid = blockIdx.x * 256 + threadIdx.x;  // 0..2047
    if (gid >= BB * DM) return;
    int b = gid >> 10;
    int d = gid & (DM - 1);

    float E64[16];
#pragma unroll
    for (int s = 0; s < 16; s++) E64[s] = expf(-(float)CHUNK * Avec[d * 16 + s]);

    float carry[16];
#pragma unroll
    for (int s = 0; s < 16; s++) carry[s] = 0.f;

    for (int c = 0; c < NCH; c++) {
        int cb = b * NCH + c;
        float pd = g_pd[(size_t)cb * DM + d];
#pragma unroll
        for (int s = 0; s < 16; s++) {
            g_hinit[((size_t)cb * 16 + s) * DM + d] = carry[s];
            carry[s] = E64[s] * pd * carry[s] + g_hend[((size_t)cb * 16 + s) * DM + d];
        }
    }
}

// ---------------- SSM scan, phase 3: replay w/ carry, fused gate+D ----------
__global__ __launch_bounds__(128) void scan_phase3(const float* __restrict__ Avec,
                                                   const float* __restrict__ Dvec)
{
    __shared__ float Bsm[CHUNK * 16];
    __shared__ float Csm[CHUNK * 16];
    int d = blockIdx.x * 128 + threadIdx.x;
    int c = blockIdx.y;
    int b = blockIdx.z;
    int base_tok = b * LL + c * CHUNK;
    int cb = b * NCH + c;

    for (int i = threadIdx.x; i < CHUNK * 16; i += 128) {
        int l = i >> 4, s = i & 15;
        Bsm[i] = g_bcd[(size_t)(base_tok + l) * 96 + s];
        Csm[i] = g_bcd[(size_t)(base_tok + l) * 96 + 16 + s];
    }
    __syncthreads();

    float E[16];
#pragma unroll
    for (int s = 0; s < 16; s++) E[s] = expf(-Avec[d * 16 + s]);

    float h[16];
#pragma unroll
    for (int s = 0; s < 16; s++)
        h[s] = g_hinit[((size_t)cb * 16 + s) * DM + d];

    float Dd = Dvec[d];

    for (int l = 0; l < CHUNK; l++) {
        int tok = base_tok + l;
        float dl = g_delta[(size_t)tok * DM + d];
        float xv = g_x[(size_t)tok * DM + d];
        float bg = g_ab[(size_t)tok * (2 * DM) + DM + d];
        float dx = dl * xv;
#pragma unroll
        for (int s = 0; s < 16; s++)
            h[s] = E[s] * dl * h[s] + Bsm[l * 16 + s] * dx;

        float y0 = 0.f, y1 = 0.f, y2 = 0.f, y3 = 0.f;
#pragma unroll
        for (int s = 0; s < 16; s += 4) {
            y0 += h[s + 0] * Csm[l * 16 + s + 0];
            y1 += h[s + 1] * Csm[l * 16 + s + 1];
            y2 += h[s + 2] * Csm[l * 16 + s + 2];
            y3 += h[s + 3] * Csm[l * 16 + s + 3];
        }
        float y = (y0 + y1) + (y2 + y3);
        float sg = 1.f / (1.f + expf(-bg));
        g_obuf[(size_t)tok * DM + d] = (y + Dd * xv) * (bg * sg);
    }
}

// ---------------- launch ------------------------------------------------------
extern "C" void kernel_launch(void* const* d_in, const int* in_sizes, int n_in,
                              void* d_out, int out_size)
{
    const float* seq    = (const float*)d_in[0];
    const float* W_in   = (const float*)d_in[1];
    const float* W_out  = (const float*)d_in[2];
    const float* W_B    = (const float*)d_in[3];
    const float* W_C    = (const float*)d_in[4];
    const float* W_D1   = (const float*)d_in[5];
    const float* W_D2   = (const float*)d_in[6];
    const float* conv_w = (const float*)d_in[7];
    const float* conv_b = (const float*)d_in[8];
    const float* Avec   = (const float*)d_in[9];
    const float* Dvec   = (const float*)d_in[10];
    float* out = (float*)d_out;

    float *ab, *xbuf, *bcd, *delta, *wbcd, *obuf;
    cudaGetSymbolAddress((void**)&ab,    g_ab);
    cudaGetSymbolAddress((void**)&xbuf,  g_x);
    cudaGetSymbolAddress((void**)&bcd,   g_bcd);
    cudaGetSymbolAddress((void**)&delta, g_delta);
    cudaGetSymbolAddress((void**)&wbcd,  g_wbcd);
    cudaGetSymbolAddress((void**)&obuf,  g_obuf);

    // 0) pack B/C/D1 weights -> [96, 1024]
    pack_w<<<(96 * DM + 255) / 256, 256>>>(W_B, W_C, W_D1);

    // 1) ab = seq @ W_in^T   (M=2048, N=2048, K=512)
    sgemm_nt<<<dim3((2 * DM) / BN, TOK / BM), 256>>>(seq, DIN, W_in, ab, TOK, 2 * DM, DIN);

    // 2) x = silu(causal_conv(a))
    conv_silu<<<(TOK * DM + 255) / 256, 256>>>(conv_w, conv_b);

    // 3) bcd = x @ [W_B;W_C;W_D1]^T   (M=2048, N=96, K=1024)
    sgemm_nt<<<dim3((96 + BN - 1) / BN, TOK / BM), 256>>>(xbuf, DM, wbcd, bcd, TOK, 96, DM);

    // 4) delta_lin = xd1 @ W_D2^T   (M=2048, N=1024, K=64); A = bcd cols 32..95
    sgemm_nt<<<dim3(DM / BN, TOK / BM), 256>>>(bcd + 32, 96, W_D2, delta, TOK, DM, DD);

    // 5) delta = softplus(D + delta_lin)
    softplus_delta<<<(TOK * DM + 255) / 256, 256>>>(Dvec);

    // 6-8) chunked scan
    scan_phase1<<<dim3(DM / 128, NCH, BB), 128>>>(Avec);
    scan_phase2<<<dim3((BB * DM + 255) / 256), 256>>>(Avec);
    scan_phase3<<<dim3(DM / 128, NCH, BB), 128>>>(Avec, Dvec);

    // 9) out = obuf @ W_out^T   (M=2048, N=512, K=1024)
    sgemm_nt<<<dim3(DIN / BN, TOK / BM), 256>>>(obuf, DM, W_out, out, TOK, DIN, DM);
}

// round 3
// speedup vs baseline: 2.3972x; 2.3972x over previous
#include <cuda_runtime.h>
#include <math.h>
#include <cstdint>

// ---------------- problem constants ------------------------------------------
#define BBATCH 2
#define LL 1024
#define DIN 512
#define DM 1024
#define DS 16
#define DD 64
#define KERW 4
#define TOK (BBATCH * LL)      // 2048
#define CHUNK 64
#define NCH (LL / CHUNK)       // 16
#define KSPLIT_BCD 4

// ---------------- scratch (static device globals) ----------------------------
__device__ __align__(16) float g_ab[TOK * 2 * DM];
__device__ __align__(16) float g_x[TOK * DM];
__device__ __align__(16) float g_bcd[TOK * 96];
__device__ __align__(16) float g_bcd_part[KSPLIT_BCD * TOK * 96];
__device__ __align__(16) float g_delta[TOK * DM];
__device__ __align__(16) float g_wbcd[96 * DM];
__device__ __align__(16) float g_hend[BBATCH * NCH * DS * DM];
__device__ __align__(16) float g_pd[BBATCH * NCH * DM];
__device__ __align__(16) float g_hinit[BBATCH * NCH * DS * DM];
__device__ __align__(16) float g_obuf[TOK * DM];

// ---------------- small PTX helpers ------------------------------------------
__device__ __forceinline__ uint32_t smem_u32(const void* p) {
    uint32_t a;
    asm("{ .reg .u64 t; cvta.to.shared.u64 t, %1; cvt.u32.u64 %0, t; }" : "=r"(a) : "l"(p));
    return a;
}
__device__ __forceinline__ uint32_t cvt_tf32(float x) {
    uint32_t o;
    asm("cvt.rna.tf32.f32 %0, %1;" : "=r"(o) : "f"(x));
    return o;
}
__device__ __forceinline__ void cp16(uint32_t dst, const void* src, int sz) {
    asm volatile("cp.async.ca.shared.global [%0], [%1], 16, %2;"
                 :: "r"(dst), "l"(src), "r"(sz) : "memory");
}
#define CP_COMMIT() asm volatile("cp.async.commit_group;" ::: "memory")
#define CP_WAIT1()  asm volatile("cp.async.wait_group 1;" ::: "memory")

__device__ __forceinline__ void mma_tf32(float* c, const uint32_t* a, uint32_t b0, uint32_t b1) {
    asm volatile(
        "mma.sync.aligned.m16n8k8.row.col.f32.tf32.tf32.f32 "
        "{%0,%1,%2,%3}, {%4,%5,%6,%7}, {%8,%9}, {%0,%1,%2,%3};"
        : "+f"(c[0]), "+f"(c[1]), "+f"(c[2]), "+f"(c[3])
        : "r"(a[0]), "r"(a[1]), "r"(a[2]), "r"(a[3]), "r"(b0), "r"(b1));
}

// ---------------- tensor-core tf32 GEMM:  C[M,N] = A[M,K] * W[N,K]^T ---------
// Block tile 128 x BNT x 32, 256 threads (8 warps: 4 along M, 2 along N).
// Warp tile 32 x (BNT/2). Double-buffered cp.async smem, stride-36 padding.
// grid = (N/BNT, M/128, ksplits)
#define BMT 128
#define BKT 32
#define PADS 36

template <int BNT>
__global__ __launch_bounds__(256) void gemm_mma(
    const float* __restrict__ A, int lda,
    const float* __restrict__ W, int ldw,
    float* __restrict__ C, int ldc,
    int Nvalid, int T, int kstride, long cstride)
{
    constexpr int NT = BNT / 16;            // n-tiles per warp (8-wide each)
    constexpr int stA = BMT * PADS;         // floats per A stage
    constexpr int stB = BNT * PADS;

    extern __shared__ float smem[];
    float* As = smem;                       // [2][BMT][PADS]
    float* Bs = smem + 2 * stA;             // [2][BNT][PADS]
    const uint32_t sbA = smem_u32(As);
    const uint32_t sbB = smem_u32(Bs);

    const int tid = threadIdx.x;
    const int lane = tid & 31;
    const int wid = tid >> 5;
    const int warp_m = wid & 3;             // 4 warps along M (32 rows each)
    const int warp_n = wid >> 2;            // 2 warps along N (BNT/2 each)
    const int bm = blockIdx.y * BMT;
    const int bn = blockIdx.x * BNT;
    const int koff = blockIdx.z * kstride;
    C += (long)blockIdx.z * cstride;

    const int gid = lane >> 2;              // 0..7
    const int tig = lane & 3;               // 0..3

    float acc[2][NT][4];
#pragma unroll
    for (int mt = 0; mt < 2; mt++)
#pragma unroll
        for (int nt = 0; nt < NT; nt++)
#pragma unroll
            for (int i = 0; i < 4; i++) acc[mt][nt][i] = 0.f;

    // ---- tile loader (cp.async) ----
    auto load_tiles = [&](int st, int t) {
        const int kc = koff + t * BKT;
#pragma unroll
        for (int j = 0; j < (BMT * 8) / 256; j++) {
            int idx = tid + j * 256;
            int row = idx >> 3, c4 = idx & 7;
            cp16(sbA + (uint32_t)(st * stA + row * PADS + c4 * 4) * 4,
                 A + (size_t)(bm + row) * lda + kc + c4 * 4, 16);
        }
#pragma unroll
        for (int j = 0; j < (BNT * 8) / 256; j++) {
            int idx = tid + j * 256;
            int row = idx >> 3, c4 = idx & 7;
            bool v = (bn + row) < Nvalid;
            cp16(sbB + (uint32_t)(st * stB + row * PADS + c4 * 4) * 4,
                 W + (size_t)(v ? bn + row : 0) * ldw + kc + c4 * 4, v ? 16 : 0);
        }
    };

    load_tiles(0, 0);
    CP_COMMIT();

    for (int t = 0; t < T; t++) {
        if (t + 1 < T) load_tiles((t + 1) & 1, t + 1);
        CP_COMMIT();
        CP_WAIT1();
        __syncthreads();

        const float* a_base = As + (t & 1) * stA;
        const float* b_base = Bs + (t & 1) * stB;
#pragma unroll
        for (int k0 = 0; k0 < 4; k0++) {
            uint32_t af[2][4];
#pragma unroll
            for (int mt = 0; mt < 2; mt++) {
                int r = warp_m * 32 + mt * 16 + gid;
                int c = k0 * 8 + tig;
                af[mt][0] = cvt_tf32(a_base[r * PADS + c]);
                af[mt][1] = cvt_tf32(a_base[(r + 8) * PADS + c]);
                af[mt][2] = cvt_tf32(a_base[r * PADS + c + 4]);
                af[mt][3] = cvt_tf32(a_base[(r + 8) * PADS + c + 4]);
            }
#pragma unroll
            for (int nt = 0; nt < NT; nt++) {
                int n = warp_n * (BNT / 2) + nt * 8 + gid;
                int c = k0 * 8 + tig;
                uint32_t b0 = cvt_tf32(b_base[n * PADS + c]);
                uint32_t b1 = cvt_tf32(b_base[n * PADS + c + 4]);
#pragma unroll
                for (int mt = 0; mt < 2; mt++)
                    mma_tf32(acc[mt][nt], af[mt], b0, b1);
            }
        }
        __syncthreads();
    }

    // ---- epilogue: direct register -> global (float2 stores) ----
#pragma unroll
    for (int mt = 0; mt < 2; mt++) {
#pragma unroll
        for (int nt = 0; nt < NT; nt++) {
            int r0 = bm + warp_m * 32 + mt * 16 + gid;
            int cN = bn + warp_n * (BNT / 2) + nt * 8 + 2 * tig;
            if (cN < Nvalid) {
                *(float2*)&C[(size_t)r0 * ldc + cN] =
                    make_float2(acc[mt][nt][0], acc[mt][nt][1]);
                *(float2*)&C[(size_t)(r0 + 8) * ldc + cN] =
                    make_float2(acc[mt][nt][2], acc[mt][nt][3]);
            }
        }
    }
}

// ---------------- reduce split-K partials for bcd ----------------------------
__global__ void reduce_bcd()
{
    int i = blockIdx.x * 256 + threadIdx.x;
    if (i >= TOK * 96) return;
    float s = 0.f;
#pragma unroll
    for (int z = 0; z < KSPLIT_BCD; z++) s += g_bcd_part[(size_t)z * TOK * 96 + i];
    g_bcd[i] = s;
}

// ---------------- pack W_B, W_C, W_D1 into one [96,1024] matrix --------------
__global__ void pack_w(const float* __restrict__ WB, const float* __restrict__ WC,
                       const float* __restrict__ WD1)
{
    int i = blockIdx.x * 256 + threadIdx.x;
    if (i < 16 * DM)       g_wbcd[i] = WB[i];
    else if (i < 32 * DM)  g_wbcd[i] = WC[i - 16 * DM];
    else if (i < 96 * DM)  g_wbcd[i] = WD1[i - 32 * DM];
}

// ---------------- causal depthwise conv (K=4) + SiLU -------------------------
__global__ void conv_silu(const float* __restrict__ cw, const float* __restrict__ cb)
{
    int idx = blockIdx.x * 256 + threadIdx.x;
    if (idx >= TOK * DM) return;
    int d = idx & (DM - 1);
    int t = idx >> 10;
    int l = t & (LL - 1);
    float acc = cb[d];
#pragma unroll
    for (int k = 0; k < KERW; k++) {
        int ll = l - (KERW - 1) + k;
        if (ll >= 0)
            acc += g_ab[(size_t)(t - l + ll) * (2 * DM) + d] * cw[d * KERW + k];
    }
    g_x[idx] = acc / (1.f + expf(-acc));
}

// ---------------- delta = softplus(D + delta_lin) ----------------------------
__global__ void softplus_delta(const float* __restrict__ Dvec)
{
    int idx = blockIdx.x * 256 + threadIdx.x;
    if (idx >= TOK * DM) return;
    int d = idx & (DM - 1);
    float z = Dvec[d] + g_delta[idx];
    g_delta[idx] = fmaxf(z, 0.f) + log1pf(expf(-fabsf(z)));
}

// ---------------- SSM scan, phase 1: per-chunk local scan --------------------
__global__ __launch_bounds__(128) void scan_phase1(const float* __restrict__ Avec)
{
    __shared__ float Bsm[CHUNK * 16];
    int d = blockIdx.x * 128 + threadIdx.x;
    int c = blockIdx.y;
    int b = blockIdx.z;
    int base_tok = b * LL + c * CHUNK;

    for (int i = threadIdx.x; i < CHUNK * 16; i += 128) {
        int l = i >> 4, s = i & 15;
        Bsm[i] = g_bcd[(size_t)(base_tok + l) * 96 + s];
    }
    __syncthreads();

    float E[16];
#pragma unroll
    for (int s = 0; s < 16; s++) E[s] = expf(-Avec[d * 16 + s]);
    float h[16];
#pragma unroll
    for (int s = 0; s < 16; s++) h[s] = 0.f;
    float pd = 1.f;

    for (int l = 0; l < CHUNK; l++) {
        int tok = base_tok + l;
        float dl = g_delta[(size_t)tok * DM + d];
        float xv = g_x[(size_t)tok * DM + d];
        float dx = dl * xv;
        pd *= dl;
#pragma unroll
        for (int s = 0; s < 16; s++)
            h[s] = E[s] * dl * h[s] + Bsm[l * 16 + s] * dx;
    }
    int cb = b * NCH + c;
    g_pd[(size_t)cb * DM + d] = pd;
#pragma unroll
    for (int s = 0; s < 16; s++)
        g_hend[((size_t)cb * 16 + s) * DM + d] = h[s];
}

// ---------------- SSM scan, phase 2: sequential chunk combine ----------------
__global__ __launch_bounds__(256) void scan_phase2(const float* __restrict__ Avec)
{
    int gid = blockIdx.x * 256 + threadIdx.x;
    if (gid >= BBATCH * DM) return;
    int b = gid >> 10;
    int d = gid & (DM - 1);

    float E64[16];
#pragma unroll
    for (int s = 0; s < 16; s++) E64[s] = expf(-(float)CHUNK * Avec[d * 16 + s]);
    float carry[16];
#pragma unroll
    for (int s = 0; s < 16; s++) carry[s] = 0.f;

    for (int c = 0; c < NCH; c++) {
        int cb = b * NCH + c;
        float pd = g_pd[(size_t)cb * DM + d];
#pragma unroll
        for (int s = 0; s < 16; s++) {
            g_hinit[((size_t)cb * 16 + s) * DM + d] = carry[s];
            carry[s] = E64[s] * pd * carry[s] + g_hend[((size_t)cb * 16 + s) * DM + d];
        }
    }
}

// ---------------- SSM scan, phase 3: replay w/ carry, fused gate+D -----------
__global__ __launch_bounds__(128) void scan_phase3(const float* __restrict__ Avec,
                                                   const float* __restrict__ Dvec)
{
    __shared__ float Bsm[CHUNK * 16];
    __shared__ float Csm[CHUNK * 16];
    int d = blockIdx.x * 128 + threadIdx.x;
    int c = blockIdx.y;
    int b = blockIdx.z;
    int base_tok = b * LL + c * CHUNK;
    int cb = b * NCH + c;

    for (int i = threadIdx.x; i < CHUNK * 16; i += 128) {
        int l = i >> 4, s = i & 15;
        Bsm[i] = g_bcd[(size_t)(base_tok + l) * 96 + s];
        Csm[i] = g_bcd[(size_t)(base_tok + l) * 96 + 16 + s];
    }
    __syncthreads();

    float E[16];
#pragma unroll
    for (int s = 0; s < 16; s++) E[s] = expf(-Avec[d * 16 + s]);
    float h[16];
#pragma unroll
    for (int s = 0; s < 16; s++)
        h[s] = g_hinit[((size_t)cb * 16 + s) * DM + d];
    float Dd = Dvec[d];

    for (int l = 0; l < CHUNK; l++) {
        int tok = base_tok + l;
        float dl = g_delta[(size_t)tok * DM + d];
        float xv = g_x[(size_t)tok * DM + d];
        float bg = g_ab[(size_t)tok * (2 * DM) + DM + d];
        float dx = dl * xv;
#pragma unroll
        for (int s = 0; s < 16; s++)
            h[s] = E[s] * dl * h[s] + Bsm[l * 16 + s] * dx;

        float y0 = 0.f, y1 = 0.f, y2 = 0.f, y3 = 0.f;
#pragma unroll
        for (int s = 0; s < 16; s += 4) {
            y0 += h[s + 0] * Csm[l * 16 + s + 0];
            y1 += h[s + 1] * Csm[l * 16 + s + 1];
            y2 += h[s + 2] * Csm[l * 16 + s + 2];
            y3 += h[s + 3] * Csm[l * 16 + s + 3];
        }
        float y = (y0 + y1) + (y2 + y3);
        float sg = 1.f / (1.f + expf(-bg));
        g_obuf[(size_t)tok * DM + d] = (y + Dd * xv) * (bg * sg);
    }
}

// ---------------- launch ------------------------------------------------------
#define SMEM_128 ((BMT + 128) * PADS * 4 * 2)
#define SMEM_64  ((BMT + 64) * PADS * 4 * 2)

extern "C" void kernel_launch(void* const* d_in, const int* in_sizes, int n_in,
                              void* d_out, int out_size)
{
    const float* seq    = (const float*)d_in[0];
    const float* W_in   = (const float*)d_in[1];
    const float* W_out  = (const float*)d_in[2];
    const float* W_B    = (const float*)d_in[3];
    const float* W_C    = (const float*)d_in[4];
    const float* W_D1   = (const float*)d_in[5];
    const float* W_D2   = (const float*)d_in[6];
    const float* conv_w = (const float*)d_in[7];
    const float* conv_b = (const float*)d_in[8];
    const float* Avec   = (const float*)d_in[9];
    const float* Dvec   = (const float*)d_in[10];
    float* out = (float*)d_out;

    float *ab, *xbuf, *bcd, *bcdp, *delta, *wbcd, *obuf;
    cudaGetSymbolAddress((void**)&ab,    g_ab);
    cudaGetSymbolAddress((void**)&xbuf,  g_x);
    cudaGetSymbolAddress((void**)&bcd,   g_bcd);
    cudaGetSymbolAddress((void**)&bcdp,  g_bcd_part);
    cudaGetSymbolAddress((void**)&delta, g_delta);
    cudaGetSymbolAddress((void**)&wbcd,  g_wbcd);
    cudaGetSymbolAddress((void**)&obuf,  g_obuf);

    cudaFuncSetAttribute(gemm_mma<128>, cudaFuncAttributeMaxDynamicSharedMemorySize, SMEM_128);
    cudaFuncSetAttribute(gemm_mma<64>,  cudaFuncAttributeMaxDynamicSharedMemorySize, SMEM_64);

    // 0) pack B/C/D1 weights -> [96, 1024]
    pack_w<<<(96 * DM + 255) / 256, 256>>>(W_B, W_C, W_D1);

    // 1) ab = seq @ W_in^T   (2048 x 2048 x 512)
    gemm_mma<128><<<dim3((2 * DM) / 128, TOK / BMT, 1), 256, SMEM_128>>>(
        seq, DIN, W_in, DIN, ab, 2 * DM, 2 * DM, DIN / BKT, 0, 0);

    // 2) x = silu(causal_conv(a))
    conv_silu<<<(TOK * DM + 255) / 256, 256>>>(conv_w, conv_b);

    // 3) bcd = x @ [W_B;W_C;W_D1]^T  (2048 x 96 x 1024), split-K=4
    gemm_mma<128><<<dim3(1, TOK / BMT, KSPLIT_BCD), 256, SMEM_128>>>(
        xbuf, DM, wbcd, DM, bcdp, 96, 96, (DM / KSPLIT_BCD) / BKT,
        DM / KSPLIT_BCD, (long)TOK * 96);
    reduce_bcd<<<(TOK * 96 + 255) / 256, 256>>>();

    // 4) delta_lin = xd1 @ W_D2^T  (2048 x 1024 x 64); xd1 = bcd cols 32..95
    gemm_mma<128><<<dim3(DM / 128, TOK / BMT, 1), 256, SMEM_128>>>(
        bcd + 32, 96, W_D2, DD, delta, DM, DM, DD / BKT, 0, 0);

    // 5) delta = softplus(D + delta_lin)
    softplus_delta<<<(TOK * DM + 255) / 256, 256>>>(Dvec);

    // 6-8) chunked scan
    scan_phase1<<<dim3(DM / 128, NCH, BBATCH), 128>>>(Avec);
    scan_phase2<<<dim3((BBATCH * DM + 255) / 256), 256>>>(Avec);
    scan_phase3<<<dim3(DM / 128, NCH, BBATCH), 128>>>(Avec, Dvec);

    // 9) out = obuf @ W_out^T  (2048 x 512 x 1024)
    gemm_mma<64><<<dim3(DIN / 64, TOK / BMT, 1), 256, SMEM_64>>>(
        obuf, DM, W_out, DM, out, DIN, DIN, DM / BKT, 0, 0);
}